// round 4
// baseline (speedup 1.0000x reference)
#include <cuda_runtime.h>
#include <cuda_bf16.h>
#include <cuda_fp8.h>
#include <cstdint>

#define N_PTS 9216
#define DD 256
#define GRID_T 72
#define NBLOCKS (GRID_T * GRID_T)
#define ASTRIDE_B 144      // bytes per smem row (128B data + 16B pad -> conflict-free LDSM)
#define POSV ((float)(1.0 / 360.0))
#define NEGV ((float)(-0.5 / 8855.0))

__device__ uint8_t g_X8[N_PTS * DD];
__device__ float g_sq[N_PTS];
__device__ float g_partials[NBLOCKS];

// ---------------- prep: fp32 -> e4m3 + fp32 row norms ----------------
__global__ void __launch_bounds__(256) prep_kernel(const float* __restrict__ images) {
    int wid = threadIdx.x >> 5, lane = threadIdx.x & 31;
    int row = blockIdx.x * 8 + wid;
    const float4* src = (const float4*)(images + (size_t)row * DD);
    float4 v0 = src[lane * 2];
    float4 v1 = src[lane * 2 + 1];
    uint32_t lo = (uint32_t)__nv_cvt_float_to_fp8(v0.x, __NV_SATFINITE, __NV_E4M3)
                | ((uint32_t)__nv_cvt_float_to_fp8(v0.y, __NV_SATFINITE, __NV_E4M3) << 8)
                | ((uint32_t)__nv_cvt_float_to_fp8(v0.z, __NV_SATFINITE, __NV_E4M3) << 16)
                | ((uint32_t)__nv_cvt_float_to_fp8(v0.w, __NV_SATFINITE, __NV_E4M3) << 24);
    uint32_t hi = (uint32_t)__nv_cvt_float_to_fp8(v1.x, __NV_SATFINITE, __NV_E4M3)
                | ((uint32_t)__nv_cvt_float_to_fp8(v1.y, __NV_SATFINITE, __NV_E4M3) << 8)
                | ((uint32_t)__nv_cvt_float_to_fp8(v1.z, __NV_SATFINITE, __NV_E4M3) << 16)
                | ((uint32_t)__nv_cvt_float_to_fp8(v1.w, __NV_SATFINITE, __NV_E4M3) << 24);
    ((uint2*)(g_X8 + (size_t)row * DD))[lane] = make_uint2(lo, hi);
    float s = v0.x * v0.x + v0.y * v0.y + v0.z * v0.z + v0.w * v0.w
            + v1.x * v1.x + v1.y * v1.y + v1.z * v1.z + v1.w * v1.w;
    #pragma unroll
    for (int o = 16; o > 0; o >>= 1) s += __shfl_xor_sync(0xffffffffu, s, o);
    if (lane == 0) g_sq[row] = s;
}

// correction = sim(d2) + 1.0027 (exact fp32 path, applied for d2 <= 36)
__device__ __forceinline__ float corr_fn(float d2) {
    d2 = fmaxf(d2, 0.0f);
    float dist = (d2 > 0.0f) ? sqrtf(d2) : 0.0f;
    float t = 5.0f * (1.0f - dist);
    float sp = (t > 0.0f) ? (t + log1pf(expf(-t))) : log1pf(expf(t));
    return 0.4f * sp;
}
__device__ __forceinline__ float maskval(int i, int j) {
    int ci0 = i / 96, ci1 = i - ci0 * 96;
    int cj0 = j / 96, cj1 = j - cj0 * 96;
    int d0 = abs(ci0 - cj0); d0 = min(d0, 96 - d0);
    int d1 = abs(ci1 - cj1); d1 = min(d1, 96 - d1);
    return (d0 <= 9 && d1 <= 9) ? POSV : NEGV;
}

// ---------------- main: fused fp8 pairwise GEMM + rare-correction ----------
__global__ void __launch_bounds__(256, 2)
pair_kernel(const float* __restrict__ images) {
    __shared__ uint8_t As[128 * ASTRIDE_B];
    __shared__ uint8_t Bs[128 * ASTRIDE_B];
    __shared__ float sSqI[128];
    __shared__ float sSqJ[128];
    __shared__ float wsum[8];

    int bx = blockIdx.x;
    int by = blockIdx.y;
    int pidx = by * GRID_T + bx;
    if (by > bx) {                        // symmetric: upper triangle of tiles only
        if (threadIdx.x == 0) g_partials[pidx] = 0.0f;
        return;
    }

    int i0 = by * 128;
    int j0 = bx * 128;
    int tid  = threadIdx.x;
    int wid  = tid >> 5;
    int lane = tid & 31;
    int g  = lane >> 2;
    int tg = lane & 3;
    int wm = (wid >> 1) * 32;   // warp m offset: 0/32/64/96
    int wn = (wid & 1) * 64;    // warp n offset: 0/64

    if (tid < 128) sSqI[tid] = g_sq[i0 + tid];
    else           sSqJ[tid - 128] = g_sq[j0 + (tid - 128)];

    // ldmatrix lane addressing (byte offsets) — identical byte math to bf16 version
    int quad = lane >> 3, rw = lane & 7;
    uint32_t As_u, Bs_u;
    asm("{ .reg .u64 t; cvta.to.shared.u64 t, %1; cvt.u32.u64 %0, t; }" : "=r"(As_u) : "l"(As));
    asm("{ .reg .u64 t; cvta.to.shared.u64 t, %1; cvt.u32.u64 %0, t; }" : "=r"(Bs_u) : "l"(Bs));
    uint32_t aAddr = As_u + (uint32_t)((wm + rw + (quad & 1) * 8) * ASTRIDE_B + (quad >> 1) * 16);
    uint32_t bAddr = Bs_u + (uint32_t)((wn + rw + ((quad >> 1) & 1) * 8) * ASTRIDE_B + (quad & 1) * 16);

    float acc[2][8][4];
    #pragma unroll
    for (int a = 0; a < 2; a++)
        #pragma unroll
        for (int b = 0; b < 8; b++)
            #pragma unroll
            for (int c = 0; c < 4; c++) acc[a][b][c] = 0.0f;

    #pragma unroll 1
    for (int kc = 0; kc < 2; kc++) {                 // two 128-byte K chunks
        #pragma unroll
        for (int v = 0; v < 4; v++) {                // 1024 x 16B per tile, 2 tiles
            int lin = tid + v * 256;
            int r  = lin >> 3;
            int c8 = lin & 7;
            const uint8_t* sa = g_X8 + (size_t)(i0 + r) * DD + kc * 128 + c8 * 16;
            const uint8_t* sb = g_X8 + (size_t)(j0 + r) * DD + kc * 128 + c8 * 16;
            uint4 dA = *(const uint4*)sa;
            uint4 dB = *(const uint4*)sb;
            *(uint4*)(As + r * ASTRIDE_B + c8 * 16) = dA;
            *(uint4*)(Bs + r * ASTRIDE_B + c8 * 16) = dB;
        }
        __syncthreads();

        #pragma unroll
        for (int ksb = 0; ksb < 128; ksb += 32) {    // 4 k32 steps per chunk
            uint32_t afr[2][4];
            #pragma unroll
            for (int mf = 0; mf < 2; mf++) {
                uint32_t ad = aAddr + (uint32_t)(mf * 16 * ASTRIDE_B + ksb);
                asm volatile("ldmatrix.sync.aligned.m8n8.x4.shared.b16 {%0,%1,%2,%3}, [%4];"
                             : "=r"(afr[mf][0]), "=r"(afr[mf][1]),
                               "=r"(afr[mf][2]), "=r"(afr[mf][3]) : "r"(ad));
            }
            uint32_t bfr[8][2];
            #pragma unroll
            for (int p = 0; p < 4; p++) {
                uint32_t bd = bAddr + (uint32_t)(p * 16 * ASTRIDE_B + ksb);
                asm volatile("ldmatrix.sync.aligned.m8n8.x4.shared.b16 {%0,%1,%2,%3}, [%4];"
                             : "=r"(bfr[2 * p][0]), "=r"(bfr[2 * p][1]),
                               "=r"(bfr[2 * p + 1][0]), "=r"(bfr[2 * p + 1][1]) : "r"(bd));
            }
            #pragma unroll
            for (int mf = 0; mf < 2; mf++)
                #pragma unroll
                for (int nf = 0; nf < 8; nf++) {
                    asm volatile(
                        "mma.sync.aligned.m16n8k32.row.col.f32.e4m3.e4m3.f32 "
                        "{%0,%1,%2,%3}, {%4,%5,%6,%7}, {%8,%9}, {%0,%1,%2,%3};\n"
                        : "+f"(acc[mf][nf][0]), "+f"(acc[mf][nf][1]),
                          "+f"(acc[mf][nf][2]), "+f"(acc[mf][nf][3])
                        : "r"(afr[mf][0]), "r"(afr[mf][1]),
                          "r"(afr[mf][2]), "r"(afr[mf][3]),
                          "r"(bfr[nf][0]), "r"(bfr[nf][1]));
                }
        }
        __syncthreads();
    }

    // ---- epilogue: detect d2_fp8 <= 128, exact-recompute rare hits ----
    float local = 0.0f;
    #pragma unroll
    for (int mf = 0; mf < 2; mf++) {
        int r0 = wm + mf * 16 + g;
        float sqa = sSqI[r0];
        float sqb = sSqI[r0 + 8];
        #pragma unroll
        for (int nf = 0; nf < 8; nf++) {
            int cl = wn + nf * 8 + 2 * tg;
            float sj0 = sSqJ[cl];
            float sj1 = sSqJ[cl + 1];
            float d00 = fmaf(-2.0f, acc[mf][nf][0], sqa + sj0);
            float d01 = fmaf(-2.0f, acc[mf][nf][1], sqa + sj1);
            float d10 = fmaf(-2.0f, acc[mf][nf][2], sqb + sj0);
            float d11 = fmaf(-2.0f, acc[mf][nf][3], sqb + sj1);
            float mn = fminf(fminf(d00, d01), fminf(d10, d11));
            if (mn <= 128.0f) {            // rare: ~diagonal fragments only
                #pragma unroll
                for (int q = 0; q < 4; q++) {
                    float d2f = (q == 0) ? d00 : (q == 1) ? d01 : (q == 2) ? d10 : d11;
                    if (d2f <= 128.0f) {
                        int i = i0 + r0 + (q >> 1) * 8;
                        int j = j0 + cl + (q & 1);
                        if (i < j) {       // count once, weight x2 (sym)
                            const float4* xa = (const float4*)(images + (size_t)i * DD);
                            const float4* xb = (const float4*)(images + (size_t)j * DD);
                            float dot = 0.0f;
                            #pragma unroll 8
                            for (int u = 0; u < 64; u++) {
                                float4 a = xa[u], b = xb[u];
                                dot = fmaf(a.x, b.x, dot); dot = fmaf(a.y, b.y, dot);
                                dot = fmaf(a.z, b.z, dot); dot = fmaf(a.w, b.w, dot);
                            }
                            float d2 = fmaxf(g_sq[i] + g_sq[j] - 2.0f * dot, 0.0f);
                            if (d2 <= 36.0f)
                                local = fmaf(2.0f * corr_fn(d2), maskval(i, j), local);
                        }
                    }
                }
            }
        }
    }

    #pragma unroll
    for (int o = 16; o > 0; o >>= 1) local += __shfl_xor_sync(0xffffffffu, local, o);
    if (lane == 0) wsum[wid] = local;
    __syncthreads();
    if (tid == 0) {
        float s = 0.0f;
        #pragma unroll
        for (int w = 0; w < 8; w++) s += wsum[w];
        g_partials[pidx] = s;
    }
}

// ---------------- final reduce + closed-form base term ---------------------
__global__ void reduce_kernel(float* __restrict__ out) {
    int t = threadIdx.x;  // 256
    float s = 0.0f;
    for (int i = t; i < NBLOCKS; i += 256) s += g_partials[i];
    #pragma unroll
    for (int o = 16; o > 0; o >>= 1) s += __shfl_xor_sync(0xffffffffu, s, o);
    __shared__ float ws[8];
    if ((t & 31) == 0) ws[t >> 5] = s;
    __syncthreads();
    if (t == 0) {
        float tot = 0.0f;
        #pragma unroll
        for (int w = 0; w < 8; w++) tot += ws[w];
        // sum(mask) = N * (360*POSV + 8855*NEGV); off-diag sim == -1.0027f (fp32-exact)
        double masksum = 9216.0 * (360.0 * (double)POSV + 8855.0 * (double)NEGV);
        double base = (double)(-1.0027f) * masksum;
        out[0] = (float)(((double)tot + base) / 9216.0);
    }
}

extern "C" void kernel_launch(void* const* d_in, const int* in_sizes, int n_in,
                              void* d_out, int out_size) {
    const float* images = (const float*)d_in[0];   // [9216,1,16,16] fp32
    (void)in_sizes; (void)n_in;
    prep_kernel<<<N_PTS / 8, 256>>>(images);
    pair_kernel<<<dim3(GRID_T, GRID_T), 256>>>(images);
    reduce_kernel<<<1, 256>>>((float*)d_out);
}

// round 5
// speedup vs baseline: 1.9895x; 1.9895x over previous
#include <cuda_runtime.h>
#include <cuda_bf16.h>
#include <cuda_fp8.h>
#include <cstdint>

#define N_PTS 9216
#define DD 256
#define KSUB 64            // screening subset: dims 0..63  (d2_full >= d2_sub)
#define GRID_T 72
#define NT 2628            // 72*73/2 triangular tiles
#define ASTR 80            // smem row stride bytes (64B data + 16B pad, conflict-free LDSM)
#define POSV ((float)(1.0 / 360.0))
#define NEGV ((float)(-0.5 / 8855.0))

__device__ uint8_t g_X8[N_PTS * KSUB];     // e4m3 of first 64 dims
__device__ float g_sq[N_PTS];              // full 256-dim fp32 norms (for rescue)
__device__ float g_sq8[N_PTS];             // subset norms of DEQUANTIZED values (exact screen)
__device__ float g_partials[NT];

// ---------------- prep: quantize 64 dims + both norms ----------------
__global__ void __launch_bounds__(256) prep_kernel(const float* __restrict__ images) {
    int wid = threadIdx.x >> 5, lane = threadIdx.x & 31;
    int row = blockIdx.x * 16 + wid * 2;           // 2 rows per warp (MLP=4)
    const float4* s0 = (const float4*)(images + (size_t)row * DD);
    const float4* s1 = (const float4*)(images + (size_t)(row + 1) * DD);
    float4 a0 = s0[lane * 2], a1 = s0[lane * 2 + 1];
    float4 b0 = s1[lane * 2], b1 = s1[lane * 2 + 1];

    float na = a0.x*a0.x + a0.y*a0.y + a0.z*a0.z + a0.w*a0.w
             + a1.x*a1.x + a1.y*a1.y + a1.z*a1.z + a1.w*a1.w;
    float nb = b0.x*b0.x + b0.y*b0.y + b0.z*b0.z + b0.w*b0.w
             + b1.x*b1.x + b1.y*b1.y + b1.z*b1.z + b1.w*b1.w;
    #pragma unroll
    for (int o = 16; o > 0; o >>= 1) {
        na += __shfl_xor_sync(0xffffffffu, na, o);
        nb += __shfl_xor_sync(0xffffffffu, nb, o);
    }
    if (lane == 0) { g_sq[row] = na; g_sq[row + 1] = nb; }

    // lanes 0..7 hold dims 8*lane .. 8*lane+7 -> quantize, dequant-square, store
    float s8a = 0.0f, s8b = 0.0f;
    if (lane < 8) {
        float va[8] = {a0.x, a0.y, a0.z, a0.w, a1.x, a1.y, a1.z, a1.w};
        float vb[8] = {b0.x, b0.y, b0.z, b0.w, b1.x, b1.y, b1.z, b1.w};
        uint32_t qa[2] = {0, 0}, qb[2] = {0, 0};
        #pragma unroll
        for (int k = 0; k < 8; k++) {
            uint8_t ea = __nv_cvt_float_to_fp8(va[k], __NV_SATFINITE, __NV_E4M3);
            uint8_t eb = __nv_cvt_float_to_fp8(vb[k], __NV_SATFINITE, __NV_E4M3);
            qa[k >> 2] |= (uint32_t)ea << ((k & 3) * 8);
            qb[k >> 2] |= (uint32_t)eb << ((k & 3) * 8);
            float da = __half2float(__nv_cvt_fp8_to_halfraw(ea, __NV_E4M3));
            float db = __half2float(__nv_cvt_fp8_to_halfraw(eb, __NV_E4M3));
            s8a = fmaf(da, da, s8a);
            s8b = fmaf(db, db, s8b);
        }
        *(uint2*)(g_X8 + (size_t)row * KSUB + lane * 8) = make_uint2(qa[0], qa[1]);
        *(uint2*)(g_X8 + (size_t)(row + 1) * KSUB + lane * 8) = make_uint2(qb[0], qb[1]);
    }
    #pragma unroll
    for (int o = 16; o > 0; o >>= 1) {
        s8a += __shfl_xor_sync(0xffffffffu, s8a, o);
        s8b += __shfl_xor_sync(0xffffffffu, s8b, o);
    }
    if (lane == 0) { g_sq8[row] = s8a; g_sq8[row + 1] = s8b; }
}

// correction = sim(d2) + 1.0027, exact fp32, applied for d2 <= 16
__device__ __forceinline__ float corr_fn(float d2) {
    d2 = fmaxf(d2, 0.0f);
    float dist = (d2 > 0.0f) ? sqrtf(d2) : 0.0f;
    float t = 5.0f * (1.0f - dist);
    float sp = (t > 0.0f) ? (t + log1pf(expf(-t))) : log1pf(expf(t));
    return 0.4f * sp;
}
__device__ __forceinline__ float maskval(int i, int j) {
    int ci0 = i / 96, ci1 = i - ci0 * 96;
    int cj0 = j / 96, cj1 = j - cj0 * 96;
    int d0 = abs(ci0 - cj0); d0 = min(d0, 96 - d0);
    int d1 = abs(ci1 - cj1); d1 = min(d1, 96 - d1);
    return (d0 <= 9 && d1 <= 9) ? POSV : NEGV;
}

// ---------------- screening GEMM (K=64 fp8) + exact rescue ----------------
__global__ void __launch_bounds__(256, 2)
pair_kernel(const float* __restrict__ images) {
    __shared__ uint8_t As[128 * ASTR];
    __shared__ uint8_t Bs[128 * ASTR];
    __shared__ float sSq8I[128];
    __shared__ float sSq8J[128];
    __shared__ float wsum[8];

    // triangular tile decode
    int t = blockIdx.x;
    int by = 0, rem = t;
    while (rem >= GRID_T - by) { rem -= GRID_T - by; by++; }
    int bx = by + rem;
    int i0 = by * 128, j0 = bx * 128;

    int tid  = threadIdx.x;
    int wid  = tid >> 5;
    int lane = tid & 31;
    int g  = lane >> 2;
    int wm = (wid >> 1) * 32;
    int wn = (wid & 1) * 64;

    if (tid < 128) sSq8I[tid] = g_sq8[i0 + tid];
    else           sSq8J[tid - 128] = g_sq8[j0 + (tid - 128)];

    // tile load: 128 rows x 64B each side; thread -> (row, 32B half)
    {
        int r = tid >> 1, h = (tid & 1) * 32;
        const uint8_t* sa = g_X8 + (size_t)(i0 + r) * KSUB + h;
        const uint8_t* sb = g_X8 + (size_t)(j0 + r) * KSUB + h;
        uint4 a0 = *(const uint4*)sa;
        uint4 a1 = *(const uint4*)(sa + 16);
        uint4 b0 = *(const uint4*)sb;
        uint4 b1 = *(const uint4*)(sb + 16);
        *(uint4*)(As + r * ASTR + h)      = a0;
        *(uint4*)(As + r * ASTR + h + 16) = a1;
        *(uint4*)(Bs + r * ASTR + h)      = b0;
        *(uint4*)(Bs + r * ASTR + h + 16) = b1;
    }
    __syncthreads();

    // ldmatrix addressing
    int quad = lane >> 3, rw = lane & 7;
    uint32_t As_u, Bs_u;
    asm("{ .reg .u64 t; cvta.to.shared.u64 t, %1; cvt.u32.u64 %0, t; }" : "=r"(As_u) : "l"(As));
    asm("{ .reg .u64 t; cvta.to.shared.u64 t, %1; cvt.u32.u64 %0, t; }" : "=r"(Bs_u) : "l"(Bs));
    uint32_t aAddr = As_u + (uint32_t)((wm + rw + (quad & 1) * 8) * ASTR + (quad >> 1) * 16);
    uint32_t bAddr = Bs_u + (uint32_t)((wn + rw + ((quad >> 1) & 1) * 8) * ASTR + (quad & 1) * 16);

    float acc[2][8][4];
    #pragma unroll
    for (int a = 0; a < 2; a++)
        #pragma unroll
        for (int b = 0; b < 8; b++)
            #pragma unroll
            for (int c = 0; c < 4; c++) acc[a][b][c] = 0.0f;

    #pragma unroll
    for (int ksb = 0; ksb < KSUB; ksb += 32) {       // 2 k32 steps
        uint32_t afr[2][4];
        #pragma unroll
        for (int mf = 0; mf < 2; mf++) {
            uint32_t ad = aAddr + (uint32_t)(mf * 16 * ASTR + ksb);
            asm volatile("ldmatrix.sync.aligned.m8n8.x4.shared.b16 {%0,%1,%2,%3}, [%4];"
                         : "=r"(afr[mf][0]), "=r"(afr[mf][1]),
                           "=r"(afr[mf][2]), "=r"(afr[mf][3]) : "r"(ad));
        }
        uint32_t bfr[8][2];
        #pragma unroll
        for (int p = 0; p < 4; p++) {
            uint32_t bd = bAddr + (uint32_t)(p * 16 * ASTR + ksb);
            asm volatile("ldmatrix.sync.aligned.m8n8.x4.shared.b16 {%0,%1,%2,%3}, [%4];"
                         : "=r"(bfr[2 * p][0]), "=r"(bfr[2 * p][1]),
                           "=r"(bfr[2 * p + 1][0]), "=r"(bfr[2 * p + 1][1]) : "r"(bd));
        }
        #pragma unroll
        for (int mf = 0; mf < 2; mf++)
            #pragma unroll
            for (int nf = 0; nf < 8; nf++) {
                asm volatile(
                    "mma.sync.aligned.m16n8k32.row.col.f32.e4m3.e4m3.f32 "
                    "{%0,%1,%2,%3}, {%4,%5,%6,%7}, {%8,%9}, {%0,%1,%2,%3};\n"
                    : "+f"(acc[mf][nf][0]), "+f"(acc[mf][nf][1]),
                      "+f"(acc[mf][nf][2]), "+f"(acc[mf][nf][3])
                    : "r"(afr[mf][0]), "r"(afr[mf][1]),
                      "r"(afr[mf][2]), "r"(afr[mf][3]),
                      "r"(bfr[nf][0]), "r"(bfr[nf][1]));
            }
    }

    // ---- epilogue: exact quantized-space screen, d2hat <= 32 => rescue ----
    // d2_full >= d2_sub(true); quantization: dhat <= d + 1.4 so d<=4 => d2hat <= 29.2 < 32
    float local = 0.0f;
    int tg = lane & 3;
    #pragma unroll
    for (int mf = 0; mf < 2; mf++) {
        int r0 = wm + mf * 16 + g;
        float sqa = sSq8I[r0];
        float sqb = sSq8I[r0 + 8];
        #pragma unroll
        for (int nf = 0; nf < 8; nf++) {
            int cl = wn + nf * 8 + 2 * tg;
            float sj0 = sSq8J[cl];
            float sj1 = sSq8J[cl + 1];
            float d00 = fmaf(-2.0f, acc[mf][nf][0], sqa + sj0);
            float d01 = fmaf(-2.0f, acc[mf][nf][1], sqa + sj1);
            float d10 = fmaf(-2.0f, acc[mf][nf][2], sqb + sj0);
            float d11 = fmaf(-2.0f, acc[mf][nf][3], sqb + sj1);
            float mn = fminf(fminf(d00, d01), fminf(d10, d11));
            if (mn <= 32.0f) {          // ~only diagonal fragments
                #pragma unroll
                for (int q = 0; q < 4; q++) {
                    float d2f = (q == 0) ? d00 : (q == 1) ? d01 : (q == 2) ? d10 : d11;
                    if (d2f <= 32.0f) {
                        int i = i0 + r0 + (q >> 1) * 8;
                        int j = j0 + cl + (q & 1);
                        if (i < j) {    // count once, weight x2 (symmetry)
                            const float4* xa = (const float4*)(images + (size_t)i * DD);
                            const float4* xb = (const float4*)(images + (size_t)j * DD);
                            float dot = 0.0f;
                            #pragma unroll 8
                            for (int u = 0; u < 64; u++) {
                                float4 a = xa[u], b = xb[u];
                                dot = fmaf(a.x, b.x, dot); dot = fmaf(a.y, b.y, dot);
                                dot = fmaf(a.z, b.z, dot); dot = fmaf(a.w, b.w, dot);
                            }
                            float d2 = fmaxf(g_sq[i] + g_sq[j] - 2.0f * dot, 0.0f);
                            if (d2 <= 16.0f)
                                local = fmaf(2.0f * corr_fn(d2), maskval(i, j), local);
                        }
                    }
                }
            }
        }
    }

    #pragma unroll
    for (int o = 16; o > 0; o >>= 1) local += __shfl_xor_sync(0xffffffffu, local, o);
    if (lane == 0) wsum[wid] = local;
    __syncthreads();
    if (tid == 0) {
        float s = 0.0f;
        #pragma unroll
        for (int w = 0; w < 8; w++) s += wsum[w];
        g_partials[blockIdx.x] = s;
    }
}

// ---------------- final reduce + closed-form base term ---------------------
__global__ void reduce_kernel(float* __restrict__ out) {
    int t = threadIdx.x;  // 256
    float s = 0.0f;
    for (int i = t; i < NT; i += 256) s += g_partials[i];
    #pragma unroll
    for (int o = 16; o > 0; o >>= 1) s += __shfl_xor_sync(0xffffffffu, s, o);
    __shared__ float ws[8];
    if ((t & 31) == 0) ws[t >> 5] = s;
    __syncthreads();
    if (t == 0) {
        float tot = 0.0f;
        #pragma unroll
        for (int w = 0; w < 8; w++) tot += ws[w];
        // off-diag sim == -1.0027f exactly; sum(mask) = N*(360*POSV + 8855*NEGV)
        double masksum = 9216.0 * (360.0 * (double)POSV + 8855.0 * (double)NEGV);
        double base = (double)(-1.0027f) * masksum;
        out[0] = (float)(((double)tot + base) / 9216.0);
    }
}

extern "C" void kernel_launch(void* const* d_in, const int* in_sizes, int n_in,
                              void* d_out, int out_size) {
    const float* images = (const float*)d_in[0];   // [9216,1,16,16] fp32
    (void)in_sizes; (void)n_in;
    prep_kernel<<<N_PTS / 16, 256>>>(images);
    pair_kernel<<<NT, 256>>>(images);
    reduce_kernel<<<1, 256>>>((float*)d_out);
}